// round 2
// baseline (speedup 1.0000x reference)
#include <cuda_runtime.h>

#define NODES 50000
#define EDGES 800000
#define HID   128

// Scratch (device-global: no allocations allowed)
__device__ float g_h[(size_t)NODES * HID];   // h, later reused as h2
__device__ float g_P[(size_t)NODES * HID];   // h @ W1[:H] + b1   (dst role)
__device__ float g_Q[(size_t)NODES * HID];   // h @ W1[H:]        (src role)
__device__ float g_S[(size_t)NODES * HID];   // scatter accumulator
__device__ int   g_deg[NODES];

typedef unsigned long long ull;

__device__ __forceinline__ ull dup2(float x) {
    ull r; asm("mov.b64 %0, {%1, %1};" : "=l"(r) : "f"(x)); return r;
}
__device__ __forceinline__ ull fma2(ull a, ull b, ull c) {
    ull d; asm("fma.rn.f32x2 %0, %1, %2, %3;" : "=l"(d) : "l"(a), "l"(b), "l"(c)); return d;
}
__device__ __forceinline__ float2 unpk(ull v) {
    float2 f; asm("mov.b64 {%0, %1}, %2;" : "=f"(f.x), "=f"(f.y) : "l"(v)); return f;
}

// ---------------------------------------------------------------------------
// C[M,128] = act( A[M,128] @ W[128,128] + rowscale[r] * bias[c] )
// Block: 256 threads, 64 rows x 128 cols. W fully staged in SMEM.
// Thread micro-tile: 4 rows x 8 cols, inner math in packed f32x2 FFMA2.
// ---------------------------------------------------------------------------
__global__ void __launch_bounds__(256, 2)
gemm128(const float* __restrict__ A, const float* __restrict__ W,
        const float* __restrict__ bias, const int* __restrict__ rowcnt,
        float* __restrict__ C, int M, int do_relu)
{
    extern __shared__ float sm[];
    float* sA = sm;             // 64 x 128
    float* sW = sm + 64 * HID;  // 128 x 128

    const int tid  = threadIdx.x;
    const int row0 = blockIdx.x * 64;

    // Stage W (16384 floats = 4096 float4)
    const float4* Wg  = (const float4*)W;
    float4*       sW4 = (float4*)sW;
#pragma unroll
    for (int i = 0; i < 16; ++i) sW4[tid + i * 256] = Wg[tid + i * 256];

    // Stage A tile (64x128 = 2048 float4), zero-fill out-of-range rows
    const float4* Ag  = (const float4*)A;
    float4*       sA4 = (float4*)sA;
#pragma unroll
    for (int i = 0; i < 8; ++i) {
        int lin = tid + i * 256;
        int r   = lin >> 5;
        int c4  = lin & 31;
        int gr  = row0 + r;
        float4 v = make_float4(0.f, 0.f, 0.f, 0.f);
        if (gr < M) v = Ag[(size_t)gr * 32 + c4];
        sA4[lin] = v;
    }
    __syncthreads();

    const int tc = tid & 15;  // col group: cols [8*tc, 8*tc+8)
    const int tm = tid >> 4;  // row group: rows [4*tm, 4*tm+4)

    ull acc[4][4];
#pragma unroll
    for (int r = 0; r < 4; ++r)
#pragma unroll
        for (int p = 0; p < 4; ++p) acc[r][p] = 0ull;

#pragma unroll 4
    for (int k4 = 0; k4 < 32; ++k4) {
        float4 a[4];
#pragma unroll
        for (int r = 0; r < 4; ++r) a[r] = sA4[(tm * 4 + r) * 32 + k4];
#pragma unroll
        for (int kk = 0; kk < 4; ++kk) {
            const int k = k4 * 4 + kk;
            const ulonglong2* rowp = (const ulonglong2*)(sW + k * HID);
            ulonglong2 u0 = rowp[tc * 2];
            ulonglong2 u1 = rowp[tc * 2 + 1];
#pragma unroll
            for (int r = 0; r < 4; ++r) {
                float as = (kk == 0) ? a[r].x : (kk == 1) ? a[r].y
                         : (kk == 2) ? a[r].z : a[r].w;
                ull ad = dup2(as);
                acc[r][0] = fma2(ad, u0.x, acc[r][0]);
                acc[r][1] = fma2(ad, u0.y, acc[r][1]);
                acc[r][2] = fma2(ad, u1.x, acc[r][2]);
                acc[r][3] = fma2(ad, u1.y, acc[r][3]);
            }
        }
    }

    // Epilogue
    float4 bb0 = make_float4(0.f, 0.f, 0.f, 0.f);
    float4 bb1 = make_float4(0.f, 0.f, 0.f, 0.f);
    if (bias) {
        bb0 = ((const float4*)bias)[tc * 2];
        bb1 = ((const float4*)bias)[tc * 2 + 1];
    }
#pragma unroll
    for (int r = 0; r < 4; ++r) {
        int gr = row0 + tm * 4 + r;
        if (gr >= M) continue;
        float sc = rowcnt ? (float)rowcnt[gr] : 1.0f;
        float2 c0 = unpk(acc[r][0]);
        float2 c1 = unpk(acc[r][1]);
        float2 c2 = unpk(acc[r][2]);
        float2 c3 = unpk(acc[r][3]);
        float4 o0 = make_float4(c0.x + sc * bb0.x, c0.y + sc * bb0.y,
                                c1.x + sc * bb0.z, c1.y + sc * bb0.w);
        float4 o1 = make_float4(c2.x + sc * bb1.x, c2.y + sc * bb1.y,
                                c3.x + sc * bb1.z, c3.y + sc * bb1.w);
        if (do_relu) {
            o0.x = fmaxf(o0.x, 0.f); o0.y = fmaxf(o0.y, 0.f);
            o0.z = fmaxf(o0.z, 0.f); o0.w = fmaxf(o0.w, 0.f);
            o1.x = fmaxf(o1.x, 0.f); o1.y = fmaxf(o1.y, 0.f);
            o1.z = fmaxf(o1.z, 0.f); o1.w = fmaxf(o1.w, 0.f);
        }
        ((float4*)C)[(size_t)gr * 32 + tc * 2]     = o0;
        ((float4*)C)[(size_t)gr * 32 + tc * 2 + 1] = o1;
    }
}

// ---------------------------------------------------------------------------
// Zero the scatter accumulator + degree counters
// ---------------------------------------------------------------------------
__global__ void __launch_bounds__(256)
zero_kernel()
{
    int idx    = blockIdx.x * blockDim.x + threadIdx.x;
    int stride = gridDim.x * blockDim.x;
    float4* S4 = (float4*)g_S;
    const int nS4 = NODES * HID / 4;
    for (int i = idx; i < nS4; i += stride)
        S4[i] = make_float4(0.f, 0.f, 0.f, 0.f);
    for (int i = idx; i < NODES; i += stride)
        g_deg[i] = 0;
}

// ---------------------------------------------------------------------------
// One warp per edge: r = relu(P[dst] + Q[src]); S[dst] += r (vector red);
// deg[dst] += 1.   edge_index is int32 (JAX x64 disabled downcasts int64).
// ---------------------------------------------------------------------------
__global__ void __launch_bounds__(256)
edge_kernel(const int* __restrict__ ei)
{
    int gw   = (blockIdx.x * blockDim.x + threadIdx.x) >> 5;
    int lane = threadIdx.x & 31;
    if (gw >= EDGES) return;

    int s = 0, d = 0;
    if (lane == 0) { s = ei[gw]; d = ei[EDGES + gw]; }
    s = __shfl_sync(0xffffffffu, s, 0);
    d = __shfl_sync(0xffffffffu, d, 0);

    const float4* p4 = (const float4*)(g_P + (size_t)d * HID);
    const float4* q4 = (const float4*)(g_Q + (size_t)s * HID);
    float4 p = p4[lane];
    float4 q = q4[lane];
    float4 r;
    r.x = fmaxf(p.x + q.x, 0.f);
    r.y = fmaxf(p.y + q.y, 0.f);
    r.z = fmaxf(p.z + q.z, 0.f);
    r.w = fmaxf(p.w + q.w, 0.f);

    float* dst = g_S + (size_t)d * HID + lane * 4;
    asm volatile("red.global.add.v4.f32 [%0], {%1, %2, %3, %4};"
                 :: "l"(dst), "f"(r.x), "f"(r.y), "f"(r.z), "f"(r.w)
                 : "memory");
    if (lane == 0) atomicAdd(&g_deg[d], 1);
}

// ---------------------------------------------------------------------------
// out[n, 0:2] = h2relu[n, :] @ Wc + bc.  One warp per node.
// ---------------------------------------------------------------------------
__global__ void __launch_bounds__(256)
out_kernel(const float* __restrict__ H2, const float* __restrict__ Wc,
           const float* __restrict__ bc, float* __restrict__ out)
{
    int gw   = (blockIdx.x * blockDim.x + threadIdx.x) >> 5;
    int lane = threadIdx.x & 31;
    if (gw >= NODES) return;

    float4 hv  = ((const float4*)(H2 + (size_t)gw * HID))[lane];
    float4 w01 = ((const float4*)Wc)[lane * 2];      // rows 4l,4l+1 (2 cols each)
    float4 w23 = ((const float4*)Wc)[lane * 2 + 1];  // rows 4l+2,4l+3

    float a0 = hv.x * w01.x + hv.y * w01.z + hv.z * w23.x + hv.w * w23.z;
    float a1 = hv.x * w01.y + hv.y * w01.w + hv.z * w23.y + hv.w * w23.w;
#pragma unroll
    for (int off = 16; off > 0; off >>= 1) {
        a0 += __shfl_xor_sync(0xffffffffu, a0, off);
        a1 += __shfl_xor_sync(0xffffffffu, a1, off);
    }
    if (lane == 0) {
        out[(size_t)gw * 2]     = a0 + bc[0];
        out[(size_t)gw * 2 + 1] = a1 + bc[1];
    }
}

// ---------------------------------------------------------------------------
extern "C" void kernel_launch(void* const* d_in, const int* in_sizes, int n_in,
                              void* d_out, int out_size)
{
    const float* x    = (const float*)d_in[0];
    const int*   ei   = (const int*)d_in[1];
    const float* W_in = (const float*)d_in[2];
    const float* b_in = (const float*)d_in[3];
    const float* W1   = (const float*)d_in[4];  // [256,128]
    const float* b1   = (const float*)d_in[5];
    const float* W2   = (const float*)d_in[6];
    const float* b2   = (const float*)d_in[7];
    const float* Wc   = (const float*)d_in[8];
    const float* bc   = (const float*)d_in[9];
    float*       out  = (float*)d_out;

    void *ph, *pP, *pQ, *pS, *pdeg;
    cudaGetSymbolAddress(&ph,   g_h);
    cudaGetSymbolAddress(&pP,   g_P);
    cudaGetSymbolAddress(&pQ,   g_Q);
    cudaGetSymbolAddress(&pS,   g_S);
    cudaGetSymbolAddress(&pdeg, g_deg);

    const size_t smem = (size_t)(64 * HID + HID * HID) * sizeof(float);  // 96 KB
    cudaFuncSetAttribute(gemm128, cudaFuncAttributeMaxDynamicSharedMemorySize,
                         (int)smem);

    const int M       = NODES;
    const int gblocks = (M + 63) / 64;

    // 0) zero accumulators
    zero_kernel<<<2048, 256>>>();
    // 1) h = relu(x @ W_in + b_in)
    gemm128<<<gblocks, 256, smem>>>(x, W_in, b_in, nullptr, (float*)ph, M, 1);
    // 2) P = h @ W1[:128] + b1   (b1 folded here)
    gemm128<<<gblocks, 256, smem>>>((const float*)ph, W1, b1, nullptr,
                                    (float*)pP, M, 0);
    // 3) Q = h @ W1[128:]
    gemm128<<<gblocks, 256, smem>>>((const float*)ph, W1 + 128 * 128, nullptr,
                                    nullptr, (float*)pQ, M, 0);
    // 4) per-edge relu + scatter-add into S, degree count
    edge_kernel<<<(EDGES * 32 + 255) / 256, 256>>>(ei);
    // 5) h2 = relu(S @ W2 + deg * b2)   (reuses g_h)
    gemm128<<<gblocks, 256, smem>>>((const float*)pS, W2, b2, (const int*)pdeg,
                                    (float*)ph, M, 1);
    // 6) out = h2 @ Wc + bc
    out_kernel<<<(NODES * 32 + 255) / 256, 256>>>((const float*)ph, Wc, bc, out);
}

// round 3
// speedup vs baseline: 1.6503x; 1.6503x over previous
#include <cuda_runtime.h>

#define NODES 50000
#define EDGES 800000
#define HID   128
#define CAP   128
#define OVFMAX 65536

// Scratch (device globals: no allocations allowed)
__device__ float g_h[(size_t)NODES * HID];   // h, later reused as h2
__device__ float g_P[(size_t)NODES * HID];   // h @ W1[:H] + b1   (dst role)
__device__ float g_Q[(size_t)NODES * HID];   // h @ W1[H:]        (src role)
__device__ float g_S[(size_t)NODES * HID];   // per-node aggregate
__device__ int   g_cnt[NODES];               // degree (by dst)
__device__ int   g_bucket[(size_t)NODES * CAP];
__device__ int2  g_ovf[OVFMAX];
__device__ int   g_novf;

typedef unsigned long long ull;

__device__ __forceinline__ ull dup2(float x) {
    ull r; asm("mov.b64 %0, {%1, %1};" : "=l"(r) : "f"(x)); return r;
}
__device__ __forceinline__ ull fma2(ull a, ull b, ull c) {
    ull d; asm("fma.rn.f32x2 %0, %1, %2, %3;" : "=l"(d) : "l"(a), "l"(b), "l"(c)); return d;
}
__device__ __forceinline__ float2 unpk(ull v) {
    float2 f; asm("mov.b64 {%0, %1}, %2;" : "=f"(f.x), "=f"(f.y) : "l"(v)); return f;
}

// ---------------------------------------------------------------------------
// C[M,128] = act( A[M,128] @ W[128,128] + rowscale[r] * bias[c] )
// Block: 256 threads -> 128 rows x 128 cols. Micro-tile 8x8.
// Thread (tm,tc): rows 8tm..8tm+7, cols {4tc..4tc+3} U {64+4tc..64+4tc+3}
// (interleaved cols -> conflict-free 256B/warp W sweeps).
// ---------------------------------------------------------------------------
__global__ void __launch_bounds__(256, 1)
gemm128(const float* __restrict__ A, const float* __restrict__ W,
        const float* __restrict__ bias, const int* __restrict__ rowcnt,
        float* __restrict__ C, int M, int do_relu)
{
    extern __shared__ float sm[];
    float* sA = sm;               // 128 x 128
    float* sW = sm + 128 * HID;   // 128 x 128

    const int tid  = threadIdx.x;
    const int row0 = blockIdx.x * 128;

    // Stage W (16384 floats = 4096 float4)
    const float4* Wg  = (const float4*)W;
    float4*       sW4 = (float4*)sW;
#pragma unroll
    for (int i = 0; i < 16; ++i) sW4[tid + i * 256] = Wg[tid + i * 256];

    // Stage A tile (128x128 = 4096 float4), zero-fill OOB rows
    const float4* Ag  = (const float4*)A;
    float4*       sA4 = (float4*)sA;
#pragma unroll
    for (int i = 0; i < 16; ++i) {
        int lin = tid + i * 256;
        int r   = lin >> 5;
        int c4  = lin & 31;
        int gr  = row0 + r;
        float4 v = make_float4(0.f, 0.f, 0.f, 0.f);
        if (gr < M) v = Ag[(size_t)gr * 32 + c4];
        sA4[lin] = v;
    }
    __syncthreads();

    const int tc = tid & 15;
    const int tm = tid >> 4;

    ull acc[8][4];
#pragma unroll
    for (int r = 0; r < 8; ++r)
#pragma unroll
        for (int p = 0; p < 4; ++p) acc[r][p] = 0ull;

#pragma unroll 2
    for (int k4 = 0; k4 < 32; ++k4) {
        float4 a[8];
#pragma unroll
        for (int r = 0; r < 8; ++r) a[r] = sA4[(tm * 8 + r) * 32 + k4];
#pragma unroll
        for (int kk = 0; kk < 4; ++kk) {
            const int k = k4 * 4 + kk;
            const ulonglong2* rowp = (const ulonglong2*)(sW + k * HID);
            ulonglong2 u0 = rowp[tc];       // cols 4tc..4tc+3
            ulonglong2 u1 = rowp[16 + tc];  // cols 64+4tc..64+4tc+3
#pragma unroll
            for (int r = 0; r < 8; ++r) {
                float as = (kk == 0) ? a[r].x : (kk == 1) ? a[r].y
                         : (kk == 2) ? a[r].z : a[r].w;
                ull ad = dup2(as);
                acc[r][0] = fma2(ad, u0.x, acc[r][0]);
                acc[r][1] = fma2(ad, u0.y, acc[r][1]);
                acc[r][2] = fma2(ad, u1.x, acc[r][2]);
                acc[r][3] = fma2(ad, u1.y, acc[r][3]);
            }
        }
    }

    // Epilogue
    float4 bb0 = make_float4(0.f, 0.f, 0.f, 0.f);
    float4 bb1 = make_float4(0.f, 0.f, 0.f, 0.f);
    if (bias) {
        bb0 = ((const float4*)bias)[tc];
        bb1 = ((const float4*)bias)[16 + tc];
    }
#pragma unroll
    for (int r = 0; r < 8; ++r) {
        int gr = row0 + tm * 8 + r;
        if (gr >= M) continue;
        float sc = rowcnt ? (float)rowcnt[gr] : 1.0f;
        float2 c0 = unpk(acc[r][0]);
        float2 c1 = unpk(acc[r][1]);
        float2 c2 = unpk(acc[r][2]);
        float2 c3 = unpk(acc[r][3]);
        float4 o0 = make_float4(c0.x + sc * bb0.x, c0.y + sc * bb0.y,
                                c1.x + sc * bb0.z, c1.y + sc * bb0.w);
        float4 o1 = make_float4(c2.x + sc * bb1.x, c2.y + sc * bb1.y,
                                c3.x + sc * bb1.z, c3.y + sc * bb1.w);
        if (do_relu) {
            o0.x = fmaxf(o0.x, 0.f); o0.y = fmaxf(o0.y, 0.f);
            o0.z = fmaxf(o0.z, 0.f); o0.w = fmaxf(o0.w, 0.f);
            o1.x = fmaxf(o1.x, 0.f); o1.y = fmaxf(o1.y, 0.f);
            o1.z = fmaxf(o1.z, 0.f); o1.w = fmaxf(o1.w, 0.f);
        }
        ((float4*)C)[(size_t)gr * 32 + tc]      = o0;
        ((float4*)C)[(size_t)gr * 32 + 16 + tc] = o1;
    }
}

// ---------------------------------------------------------------------------
__global__ void __launch_bounds__(256)
zero_kernel()
{
    int idx    = blockIdx.x * blockDim.x + threadIdx.x;
    int stride = gridDim.x * blockDim.x;
    for (int i = idx; i < NODES; i += stride) g_cnt[i] = 0;
    if (idx == 0) g_novf = 0;
}

// ---------------------------------------------------------------------------
// Pass 1: bucket each edge's src under its dst. Thread per edge.
// ---------------------------------------------------------------------------
__global__ void __launch_bounds__(256)
bucket_kernel(const int* __restrict__ ei)
{
    int e = blockIdx.x * blockDim.x + threadIdx.x;
    if (e >= EDGES) return;
    int s = ei[e];
    int d = ei[EDGES + e];
    int slot = atomicAdd(&g_cnt[d], 1);
    if (slot < CAP) {
        g_bucket[(size_t)d * CAP + slot] = s;
    } else {
        int o = atomicAdd(&g_novf, 1);
        if (o < OVFMAX) g_ovf[o] = make_int2(s, d);
    }
}

// ---------------------------------------------------------------------------
// Pass 2: warp per node. acc = sum_i relu(P[d] + Q[src_i]); S[d] = acc.
// ---------------------------------------------------------------------------
__global__ void __launch_bounds__(256)
node_kernel()
{
    int d    = (blockIdx.x * blockDim.x + threadIdx.x) >> 5;
    int lane = threadIdx.x & 31;
    if (d >= NODES) return;

    int n = g_cnt[d];
    if (n > CAP) n = CAP;

    float4 p = ((const float4*)(g_P + (size_t)d * HID))[lane];
    float4 acc = make_float4(0.f, 0.f, 0.f, 0.f);

    const int* bkt = g_bucket + (size_t)d * CAP;
#pragma unroll 2
    for (int i = 0; i < n; ++i) {
        int s = __ldg(bkt + i);
        float4 q = ((const float4*)(g_Q + (size_t)s * HID))[lane];
        acc.x += fmaxf(p.x + q.x, 0.f);
        acc.y += fmaxf(p.y + q.y, 0.f);
        acc.z += fmaxf(p.z + q.z, 0.f);
        acc.w += fmaxf(p.w + q.w, 0.f);
    }
    ((float4*)(g_S + (size_t)d * HID))[lane] = acc;
}

// ---------------------------------------------------------------------------
// Fixup for bucket overflow (expected empty). Warp per overflow edge.
// ---------------------------------------------------------------------------
__global__ void __launch_bounds__(256)
fixup_kernel()
{
    int total = g_novf;
    if (total > OVFMAX) total = OVFMAX;
    int gw    = (blockIdx.x * blockDim.x + threadIdx.x) >> 5;
    int nw    = (gridDim.x * blockDim.x) >> 5;
    int lane  = threadIdx.x & 31;

    for (int j = gw; j < total; j += nw) {
        int2 e = g_ovf[j];
        float4 p = ((const float4*)(g_P + (size_t)e.y * HID))[lane];
        float4 q = ((const float4*)(g_Q + (size_t)e.x * HID))[lane];
        float4 r;
        r.x = fmaxf(p.x + q.x, 0.f);
        r.y = fmaxf(p.y + q.y, 0.f);
        r.z = fmaxf(p.z + q.z, 0.f);
        r.w = fmaxf(p.w + q.w, 0.f);
        float* dst = g_S + (size_t)e.y * HID + lane * 4;
        asm volatile("red.global.add.v4.f32 [%0], {%1, %2, %3, %4};"
                     :: "l"(dst), "f"(r.x), "f"(r.y), "f"(r.z), "f"(r.w)
                     : "memory");
    }
}

// ---------------------------------------------------------------------------
// out[n, 0:2] = h2relu[n, :] @ Wc + bc.  One warp per node.
// ---------------------------------------------------------------------------
__global__ void __launch_bounds__(256)
out_kernel(const float* __restrict__ H2, const float* __restrict__ Wc,
           const float* __restrict__ bc, float* __restrict__ out)
{
    int gw   = (blockIdx.x * blockDim.x + threadIdx.x) >> 5;
    int lane = threadIdx.x & 31;
    if (gw >= NODES) return;

    float4 hv  = ((const float4*)(H2 + (size_t)gw * HID))[lane];
    float4 w01 = ((const float4*)Wc)[lane * 2];
    float4 w23 = ((const float4*)Wc)[lane * 2 + 1];

    float a0 = hv.x * w01.x + hv.y * w01.z + hv.z * w23.x + hv.w * w23.z;
    float a1 = hv.x * w01.y + hv.y * w01.w + hv.z * w23.y + hv.w * w23.w;
#pragma unroll
    for (int off = 16; off > 0; off >>= 1) {
        a0 += __shfl_xor_sync(0xffffffffu, a0, off);
        a1 += __shfl_xor_sync(0xffffffffu, a1, off);
    }
    if (lane == 0) {
        out[(size_t)gw * 2]     = a0 + bc[0];
        out[(size_t)gw * 2 + 1] = a1 + bc[1];
    }
}

// ---------------------------------------------------------------------------
extern "C" void kernel_launch(void* const* d_in, const int* in_sizes, int n_in,
                              void* d_out, int out_size)
{
    const float* x    = (const float*)d_in[0];
    const int*   ei   = (const int*)d_in[1];
    const float* W_in = (const float*)d_in[2];
    const float* b_in = (const float*)d_in[3];
    const float* W1   = (const float*)d_in[4];  // [256,128]
    const float* b1   = (const float*)d_in[5];
    const float* W2   = (const float*)d_in[6];
    const float* b2   = (const float*)d_in[7];
    const float* Wc   = (const float*)d_in[8];
    const float* bc   = (const float*)d_in[9];
    float*       out  = (float*)d_out;

    void *ph, *pP, *pQ, *pS, *pcnt;
    cudaGetSymbolAddress(&ph,   g_h);
    cudaGetSymbolAddress(&pP,   g_P);
    cudaGetSymbolAddress(&pQ,   g_Q);
    cudaGetSymbolAddress(&pS,   g_S);
    cudaGetSymbolAddress(&pcnt, g_cnt);

    const size_t smem = (size_t)(2 * HID * HID) * sizeof(float);  // 128 KB
    cudaFuncSetAttribute(gemm128, cudaFuncAttributeMaxDynamicSharedMemorySize,
                         (int)smem);

    const int M       = NODES;
    const int gblocks = (M + 127) / 128;

    // 0) zero degree counters + overflow count
    zero_kernel<<<256, 256>>>();
    // 1) bucket edges by dst
    bucket_kernel<<<(EDGES + 255) / 256, 256>>>(ei);
    // 2) h = relu(x @ W_in + b_in)
    gemm128<<<gblocks, 256, smem>>>(x, W_in, b_in, nullptr, (float*)ph, M, 1);
    // 3) P = h @ W1[:128] + b1
    gemm128<<<gblocks, 256, smem>>>((const float*)ph, W1, b1, nullptr,
                                    (float*)pP, M, 0);
    // 4) Q = h @ W1[128:]
    gemm128<<<gblocks, 256, smem>>>((const float*)ph, W1 + 128 * 128, nullptr,
                                    nullptr, (float*)pQ, M, 0);
    // 5) per-node aggregation S[d] = sum relu(P[d] + Q[src])
    node_kernel<<<(NODES * 32 + 255) / 256, 256>>>();
    // 6) overflow fixup (expected no-op)
    fixup_kernel<<<64, 256>>>();
    // 7) h2 = relu(S @ W2 + deg * b2)   (reuses g_h)
    gemm128<<<gblocks, 256, smem>>>((const float*)pS, W2, b2, (const int*)pcnt,
                                    (float*)ph, M, 1);
    // 8) out = h2 @ Wc + bc
    out_kernel<<<(NODES * 32 + 255) / 256, 256>>>((const float*)ph, Wc, bc, out);
}

// round 5
// speedup vs baseline: 1.6928x; 1.0258x over previous
#include <cuda_runtime.h>

#define NODES 50000
#define EDGES 800000
#define HID   128
#define CAP   128
#define OVFMAX 65536

// Scratch (device globals: no allocations allowed)
__device__ float g_h[(size_t)NODES * HID];   // h, later reused as h2
__device__ float g_P[(size_t)NODES * HID];   // h @ W1[:H] + b1   (dst role)
__device__ float g_Q[(size_t)NODES * HID];   // h @ W1[H:]        (src role)
__device__ float g_S[(size_t)NODES * HID];   // per-node aggregate
__device__ int   g_cnt[NODES];               // degree (by dst)
__device__ int   g_bucket[(size_t)NODES * CAP];
__device__ int2  g_ovf[OVFMAX];
__device__ int   g_novf;

typedef unsigned long long ull;

__device__ __forceinline__ ull dup2(float x) {
    ull r; asm("mov.b64 %0, {%1, %1};" : "=l"(r) : "f"(x)); return r;
}
__device__ __forceinline__ ull fma2(ull a, ull b, ull c) {
    ull d; asm("fma.rn.f32x2 %0, %1, %2, %3;" : "=l"(d) : "l"(a), "l"(b), "l"(c)); return d;
}
__device__ __forceinline__ float2 unpk(ull v) {
    float2 f; asm("mov.b64 {%0, %1}, %2;" : "=f"(f.x), "=f"(f.y) : "l"(v)); return f;
}

// ---------------------------------------------------------------------------
// C[M,128] = act( A[M,128] @ W[128,128] + rowscale[r] * bias[c] )
// Block: 256 threads -> 64 rows x 128 cols. Micro-tile 4x8.
// Thread (tm,tc): rows 4tm..4tm+3, cols {4tc..4tc+3} U {64+4tc..64+4tc+3}
// (interleaved cols -> conflict-free 256B/warp W sweeps; A is 16-way bcast).
// 96KB smem -> 2 CTAs/SM -> 16 warps/SM for latency hiding.
// ---------------------------------------------------------------------------
__global__ void __launch_bounds__(256, 2)
gemm128(const float* __restrict__ A, const float* __restrict__ W,
        const float* __restrict__ bias, const int* __restrict__ rowcnt,
        float* __restrict__ C, int M, int do_relu)
{
    extern __shared__ float sm[];
    float* sA = sm;              // 64 x 128
    float* sW = sm + 64 * HID;   // 128 x 128

    const int tid  = threadIdx.x;
    const int row0 = blockIdx.x * 64;

    // Stage W (16384 floats = 4096 float4)
    const float4* Wg  = (const float4*)W;
    float4*       sW4 = (float4*)sW;
#pragma unroll
    for (int i = 0; i < 16; ++i) sW4[tid + i * 256] = Wg[tid + i * 256];

    // Stage A tile (64x128 = 2048 float4), zero-fill OOB rows
    const float4* Ag  = (const float4*)A;
    float4*       sA4 = (float4*)sA;
#pragma unroll
    for (int i = 0; i < 8; ++i) {
        int lin = tid + i * 256;
        int r   = lin >> 5;
        int c4  = lin & 31;
        int gr  = row0 + r;
        float4 v = make_float4(0.f, 0.f, 0.f, 0.f);
        if (gr < M) v = Ag[(size_t)gr * 32 + c4];
        sA4[lin] = v;
    }
    __syncthreads();

    const int tc = tid & 15;
    const int tm = tid >> 4;

    ull acc[4][4];
#pragma unroll
    for (int r = 0; r < 4; ++r)
#pragma unroll
        for (int p = 0; p < 4; ++p) acc[r][p] = 0ull;

#pragma unroll 4
    for (int k4 = 0; k4 < 32; ++k4) {
        float4 a[4];
#pragma unroll
        for (int r = 0; r < 4; ++r) a[r] = sA4[(tm * 4 + r) * 32 + k4];
#pragma unroll
        for (int kk = 0; kk < 4; ++kk) {
            const int k = k4 * 4 + kk;
            const ulonglong2* rowp = (const ulonglong2*)(sW + k * HID);
            ulonglong2 u0 = rowp[tc];       // cols 4tc..4tc+3
            ulonglong2 u1 = rowp[16 + tc];  // cols 64+4tc..64+4tc+3
#pragma unroll
            for (int r = 0; r < 4; ++r) {
                float as = (kk == 0) ? a[r].x : (kk == 1) ? a[r].y
                         : (kk == 2) ? a[r].z : a[r].w;
                ull ad = dup2(as);
                acc[r][0] = fma2(ad, u0.x, acc[r][0]);
                acc[r][1] = fma2(ad, u0.y, acc[r][1]);
                acc[r][2] = fma2(ad, u1.x, acc[r][2]);
                acc[r][3] = fma2(ad, u1.y, acc[r][3]);
            }
        }
    }

    // Epilogue
    float4 bb0 = make_float4(0.f, 0.f, 0.f, 0.f);
    float4 bb1 = make_float4(0.f, 0.f, 0.f, 0.f);
    if (bias) {
        bb0 = ((const float4*)bias)[tc];
        bb1 = ((const float4*)bias)[16 + tc];
    }
#pragma unroll
    for (int r = 0; r < 4; ++r) {
        int gr = row0 + tm * 4 + r;
        if (gr >= M) continue;
        float sc = rowcnt ? (float)rowcnt[gr] : 1.0f;
        float2 c0 = unpk(acc[r][0]);
        float2 c1 = unpk(acc[r][1]);
        float2 c2 = unpk(acc[r][2]);
        float2 c3 = unpk(acc[r][3]);
        float4 o0 = make_float4(c0.x + sc * bb0.x, c0.y + sc * bb0.y,
                                c1.x + sc * bb0.z, c1.y + sc * bb0.w);
        float4 o1 = make_float4(c2.x + sc * bb1.x, c2.y + sc * bb1.y,
                                c3.x + sc * bb1.z, c3.y + sc * bb1.w);
        if (do_relu) {
            o0.x = fmaxf(o0.x, 0.f); o0.y = fmaxf(o0.y, 0.f);
            o0.z = fmaxf(o0.z, 0.f); o0.w = fmaxf(o0.w, 0.f);
            o1.x = fmaxf(o1.x, 0.f); o1.y = fmaxf(o1.y, 0.f);
            o1.z = fmaxf(o1.z, 0.f); o1.w = fmaxf(o1.w, 0.f);
        }
        ((float4*)C)[(size_t)gr * 32 + tc]      = o0;
        ((float4*)C)[(size_t)gr * 32 + 16 + tc] = o1;
    }
}

// ---------------------------------------------------------------------------
__global__ void __launch_bounds__(256)
zero_kernel()
{
    int idx    = blockIdx.x * blockDim.x + threadIdx.x;
    int stride = gridDim.x * blockDim.x;
    for (int i = idx; i < NODES; i += stride) g_cnt[i] = 0;
    if (idx == 0) g_novf = 0;
}

// ---------------------------------------------------------------------------
__global__ void __launch_bounds__(256)
bucket_kernel(const int* __restrict__ ei)
{
    int e = blockIdx.x * blockDim.x + threadIdx.x;
    if (e >= EDGES) return;
    int s = ei[e];
    int d = ei[EDGES + e];
    int slot = atomicAdd(&g_cnt[d], 1);
    if (slot < CAP) {
        g_bucket[(size_t)d * CAP + slot] = s;
    } else {
        int o = atomicAdd(&g_novf, 1);
        if (o < OVFMAX) g_ovf[o] = make_int2(s, d);
    }
}

// ---------------------------------------------------------------------------
__global__ void __launch_bounds__(256)
node_kernel()
{
    int d    = (blockIdx.x * blockDim.x + threadIdx.x) >> 5;
    int lane = threadIdx.x & 31;
    if (d >= NODES) return;

    int n = g_cnt[d];
    if (n > CAP) n = CAP;

    float4 p = ((const float4*)(g_P + (size_t)d * HID))[lane];
    float4 acc = make_float4(0.f, 0.f, 0.f, 0.f);

    const int* bkt = g_bucket + (size_t)d * CAP;
#pragma unroll 2
    for (int i = 0; i < n; ++i) {
        int s = __ldg(bkt + i);
        float4 q = ((const float4*)(g_Q + (size_t)s * HID))[lane];
        acc.x += fmaxf(p.x + q.x, 0.f);
        acc.y += fmaxf(p.y + q.y, 0.f);
        acc.z += fmaxf(p.z + q.z, 0.f);
        acc.w += fmaxf(p.w + q.w, 0.f);
    }
    ((float4*)(g_S + (size_t)d * HID))[lane] = acc;
}

// ---------------------------------------------------------------------------
__global__ void __launch_bounds__(256)
fixup_kernel()
{
    int total = g_novf;
    if (total > OVFMAX) total = OVFMAX;
    int gw   = (blockIdx.x * blockDim.x + threadIdx.x) >> 5;
    int nw   = (gridDim.x * blockDim.x) >> 5;
    int lane = threadIdx.x & 31;

    for (int j = gw; j < total; j += nw) {
        int2 e = g_ovf[j];
        float4 p = ((const float4*)(g_P + (size_t)e.y * HID))[lane];
        float4 q = ((const float4*)(g_Q + (size_t)e.x * HID))[lane];
        float4 r;
        r.x = fmaxf(p.x + q.x, 0.f);
        r.y = fmaxf(p.y + q.y, 0.f);
        r.z = fmaxf(p.z + q.z, 0.f);
        r.w = fmaxf(p.w + q.w, 0.f);
        float* dst = g_S + (size_t)e.y * HID + lane * 4;
        asm volatile("red.global.add.v4.f32 [%0], {%1, %2, %3, %4};"
                     :: "l"(dst), "f"(r.x), "f"(r.y), "f"(r.z), "f"(r.w)
                     : "memory");
    }
}

// ---------------------------------------------------------------------------
__global__ void __launch_bounds__(256)
out_kernel(const float* __restrict__ H2, const float* __restrict__ Wc,
           const float* __restrict__ bc, float* __restrict__ out)
{
    int gw   = (blockIdx.x * blockDim.x + threadIdx.x) >> 5;
    int lane = threadIdx.x & 31;
    if (gw >= NODES) return;

    float4 hv  = ((const float4*)(H2 + (size_t)gw * HID))[lane];
    float4 w01 = ((const float4*)Wc)[lane * 2];
    float4 w23 = ((const float4*)Wc)[lane * 2 + 1];

    float a0 = hv.x * w01.x + hv.y * w01.z + hv.z * w23.x + hv.w * w23.z;
    float a1 = hv.x * w01.y + hv.y * w01.w + hv.z * w23.y + hv.w * w23.w;
#pragma unroll
    for (int off = 16; off > 0; off >>= 1) {
        a0 += __shfl_xor_sync(0xffffffffu, a0, off);
        a1 += __shfl_xor_sync(0xffffffffu, a1, off);
    }
    if (lane == 0) {
        out[(size_t)gw * 2]     = a0 + bc[0];
        out[(size_t)gw * 2 + 1] = a1 + bc[1];
    }
}

// ---------------------------------------------------------------------------
extern "C" void kernel_launch(void* const* d_in, const int* in_sizes, int n_in,
                              void* d_out, int out_size)
{
    const float* x    = (const float*)d_in[0];
    const int*   ei   = (const int*)d_in[1];
    const float* W_in = (const float*)d_in[2];
    const float* b_in = (const float*)d_in[3];
    const float* W1   = (const float*)d_in[4];  // [256,128]
    const float* b1   = (const float*)d_in[5];
    const float* W2   = (const float*)d_in[6];
    const float* b2   = (const float*)d_in[7];
    const float* Wc   = (const float*)d_in[8];
    const float* bc   = (const float*)d_in[9];
    float*       out  = (float*)d_out;

    void *ph, *pP, *pQ, *pS, *pcnt;
    cudaGetSymbolAddress(&ph,   g_h);
    cudaGetSymbolAddress(&pP,   g_P);
    cudaGetSymbolAddress(&pQ,   g_Q);
    cudaGetSymbolAddress(&pS,   g_S);
    cudaGetSymbolAddress(&pcnt, g_cnt);

    const size_t smem = (size_t)(64 * HID + HID * HID) * sizeof(float);  // 96 KB
    cudaFuncSetAttribute(gemm128, cudaFuncAttributeMaxDynamicSharedMemorySize,
                         (int)smem);

    const int M       = NODES;
    const int gblocks = (M + 63) / 64;   // 782

    // 0) zero degree counters + overflow count
    zero_kernel<<<256, 256>>>();
    // 1) bucket edges by dst
    bucket_kernel<<<(EDGES + 255) / 256, 256>>>(ei);
    // 2) h = relu(x @ W_in + b_in)
    gemm128<<<gblocks, 256, smem>>>(x, W_in, b_in, nullptr, (float*)ph, M, 1);
    // 3) P = h @ W1[:128] + b1
    gemm128<<<gblocks, 256, smem>>>((const float*)ph, W1, b1, nullptr,
                                    (float*)pP, M, 0);
    // 4) Q = h @ W1[128:]
    gemm128<<<gblocks, 256, smem>>>((const float*)ph, W1 + 128 * 128, nullptr,
                                    nullptr, (float*)pQ, M, 0);
    // 5) per-node aggregation S[d] = sum relu(P[d] + Q[src])
    node_kernel<<<(NODES * 32 + 255) / 256, 256>>>();
    // 6) overflow fixup (expected no-op)
    fixup_kernel<<<64, 256>>>();
    // 7) h2 = relu(S @ W2 + deg * b2)   (reuses g_h)
    gemm128<<<gblocks, 256, smem>>>((const float*)pS, W2, b2, (const int*)pcnt,
                                    (float*)ph, M, 1);
    // 8) out = h2 @ Wc + bc
    out_kernel<<<(NODES * 32 + 255) / 256, 256>>>((const float*)ph, Wc, bc, out);
}

// round 6
// speedup vs baseline: 1.8329x; 1.0827x over previous
#include <cuda_runtime.h>
#include <cuda_bf16.h>
#include <cstdint>

#define NODES 50000
#define EDGES 800000
#define HID   128
#define CAP   128
#define OVFMAX 65536

// ---------------------------------------------------------------------------
// Device-global scratch (no allocations allowed)
// ---------------------------------------------------------------------------
__device__ float g_h[(size_t)NODES * HID];
__device__ float g_P[(size_t)NODES * HID];
__device__ float g_Q[(size_t)NODES * HID];
__device__ float g_S[(size_t)NODES * HID];
__device__ int   g_cnt[NODES];
__device__ int   g_bucket[(size_t)NODES * CAP];
__device__ int2  g_ovf[OVFMAX];
__device__ int   g_novf;

// Pre-transposed, bf16 hi/lo split, smem-swizzled weight images.
// Layout: hi block (N*256 bytes) then lo block. Element (n,k) at byte
// off = n*256 + ((k>>6)<<7) + (((k&63)<<1) ^ ((n&7)<<4)).
__device__ uint4 g_iWin[4096];   // Wt_in 128x128: 64 KB
__device__ uint4 g_iW1 [8192];   // Wt1 256x128:  128 KB
__device__ uint4 g_iW2 [4096];   // Wt2 128x128:  64 KB
__device__ float g_bias256[256]; // [b1 ; zeros]

__device__ __forceinline__ uint32_t smem_u32(const void* p) {
    uint32_t a;
    asm("{ .reg .u64 t; cvta.to.shared.u64 t, %1; cvt.u32.u64 %0, t; }"
        : "=r"(a) : "l"(p));
    return a;
}
__device__ __forceinline__ unsigned packbf(float x, float y) {
    __nv_bfloat162 t = __floats2bfloat162_rn(x, y);
    return *reinterpret_cast<unsigned*>(&t);
}
__device__ __forceinline__ void ldsm4(unsigned* r, uint32_t addr) {
    asm volatile("ldmatrix.sync.aligned.m8n8.x4.shared.b16 {%0,%1,%2,%3}, [%4];"
                 : "=r"(r[0]), "=r"(r[1]), "=r"(r[2]), "=r"(r[3]) : "r"(addr));
}
__device__ __forceinline__ void mma16816(float* d, const unsigned* a,
                                         unsigned b0, unsigned b1) {
    asm volatile(
        "mma.sync.aligned.m16n8k16.row.col.f32.bf16.bf16.f32 "
        "{%0,%1,%2,%3},{%4,%5,%6,%7},{%8,%9},{%0,%1,%2,%3};"
        : "+f"(d[0]), "+f"(d[1]), "+f"(d[2]), "+f"(d[3])
        : "r"(a[0]), "r"(a[1]), "r"(a[2]), "r"(a[3]), "r"(b0), "r"(b1));
}

// ---------------------------------------------------------------------------
// Prep: build weight images + bias256
// ---------------------------------------------------------------------------
__device__ __forceinline__ void img_write(uint4* img, int N, int n, int k, float v) {
    __nv_bfloat16 hi = __float2bfloat16(v);
    float hf = __bfloat162float(hi);
    __nv_bfloat16 lo = __float2bfloat16(v - hf);
    uint32_t off = (uint32_t)n * 256 + ((k >> 6) << 7) +
                   ((((k & 63) << 1)) ^ ((n & 7) << 4));
    __nv_bfloat16* p = (__nv_bfloat16*)img;
    p[off >> 1]             = hi;
    p[N * 128 + (off >> 1)] = lo;
}

__global__ void __launch_bounds__(256)
prep_kernel(const float* __restrict__ W_in, const float* __restrict__ W1,
            const float* __restrict__ W2, const float* __restrict__ b1)
{
    int idx = blockIdx.x * blockDim.x + threadIdx.x;
    if (idx < 256) g_bias256[idx] = (idx < 128) ? b1[idx] : 0.0f;

    if (idx < 16384) {                       // Wt_in[n][k] = W_in[k][n]
        int n = idx >> 7, k = idx & 127;
        img_write(g_iWin, 128, n, k, W_in[k * 128 + n]);
    } else if (idx < 49152) {                // Wt1: n<128 -> W1[k][n]; else W1[128+k][n-128]
        int t = idx - 16384;
        int n = t >> 7, k = t & 127;
        float v = (n < 128) ? W1[k * 128 + n] : W1[(128 + k) * 128 + (n - 128)];
        img_write(g_iW1, 256, n, k, v);
    } else if (idx < 65536) {                // Wt2[n][k] = W2[k][n]
        int t = idx - 49152;
        int n = t >> 7, k = t & 127;
        img_write(g_iW2, 128, n, k, W2[k * 128 + n]);
    }
}

// ---------------------------------------------------------------------------
// HMMA GEMM. CTA tile (MG*64) x (NG*64); 8 warps, each 64x64.
// 3-term bf16 split: AhWh + AlWh + AhWl. Persistent over tiles; W in smem once.
// ---------------------------------------------------------------------------
template<int MG, int NG>
__global__ void __launch_bounds__(256, 1)
mma_gemm(const float* __restrict__ A, const uint4* __restrict__ Wimg,
         const float* __restrict__ bias, const int* __restrict__ rowcnt,
         float* __restrict__ C0, float* __restrict__ C1,
         int M, int ntiles, int do_relu)
{
    constexpr int MT = MG * 64;
    constexpr int NT = NG * 64;
    extern __shared__ char smem[];
    const uint32_t sb  = smem_u32(smem);
    const uint32_t sAh = sb;
    const uint32_t sAl = sb + MT * 256;
    const uint32_t sWh = sb + MT * 512;
    const uint32_t sWl = sWh + NT * 256;

    const int tid = threadIdx.x;
    const int wid = tid >> 5;
    const int L   = tid & 31;
    const int warpM = (NG == 2) ? (wid >> 1) : (wid >> 2);
    const int warpN = (NG == 2) ? (wid & 1) : (wid & 3);

    // Stage weight image once (hi+lo): NT*512 bytes
    {
        uint4* dst = (uint4*)(smem + MT * 512);
        for (int i = tid; i < NT * 32; i += 256) dst[i] = Wimg[i];
    }

    // per-lane frag addressing constants
    const int fi   = L & 15;
    const int fkc  = L >> 4;
    const int fswz = (fi & 7) << 4;
    // staging constants
    const int sseg = (L >> 4) << 7;
    const int sx   = (L & 15) * 8;

    for (int tile = blockIdx.x; tile < ntiles; tile += gridDim.x) {
        const int m0 = tile * MT;
        __syncthreads();   // previous-iter readers done; W copy ordered (iter 0)

        // Stage A tile: warp w handles rows [w*MT/8, (w+1)*MT/8)
        const int rpw = MT / 8;
#pragma unroll 4
        for (int i = 0; i < rpw; ++i) {
            int r  = wid * rpw + i;
            int gr = m0 + r;
            float4 v = make_float4(0.f, 0.f, 0.f, 0.f);
            if (gr < M) v = ((const float4*)A)[(size_t)gr * 32 + L];
            float hx = __bfloat162float(__float2bfloat16(v.x));
            float hy = __bfloat162float(__float2bfloat16(v.y));
            float hz = __bfloat162float(__float2bfloat16(v.z));
            float hw = __bfloat162float(__float2bfloat16(v.w));
            uint2 hh = make_uint2(packbf(v.x, v.y), packbf(v.z, v.w));
            uint2 ll = make_uint2(packbf(v.x - hx, v.y - hy),
                                  packbf(v.z - hz, v.w - hw));
            uint32_t off = (uint32_t)r * 256 + sseg + (sx ^ ((r & 7) << 4));
            *(uint2*)(smem + off)            = hh;
            *(uint2*)(smem + MT * 256 + off) = ll;
        }
        __syncthreads();

        float acc[4][8][4];
#pragma unroll
        for (int mt = 0; mt < 4; ++mt)
#pragma unroll
            for (int ns = 0; ns < 8; ++ns)
#pragma unroll
                for (int e = 0; e < 4; ++e) acc[mt][ns][e] = 0.f;

#pragma unroll
        for (int t = 0; t < 3; ++t) {
            const uint32_t ab = (t == 1) ? sAl : sAh;
            const uint32_t wb = (t == 2) ? sWl : sWh;
#pragma unroll
            for (int ks = 0; ks < 8; ++ks) {
                const int k8 = ks * 16 + fkc * 8;
                const uint32_t koff = ((k8 >> 6) << 7) + (((k8 & 63) << 1) ^ fswz);
                unsigned a[4][4], bt[4][4];
#pragma unroll
                for (int mt = 0; mt < 4; ++mt) {
                    int r = warpM * 64 + mt * 16 + fi;
                    ldsm4(a[mt], ab + (uint32_t)r * 256 + koff);
                }
#pragma unroll
                for (int nt = 0; nt < 4; ++nt) {
                    int n = warpN * 64 + nt * 16 + fi;
                    ldsm4(bt[nt], wb + (uint32_t)n * 256 + koff);
                }
#pragma unroll
                for (int mt = 0; mt < 4; ++mt)
#pragma unroll
                    for (int nt = 0; nt < 4; ++nt) {
                        mma16816(acc[mt][nt * 2],     a[mt], bt[nt][0], bt[nt][2]);
                        mma16816(acc[mt][nt * 2 + 1], a[mt], bt[nt][1], bt[nt][3]);
                    }
            }
        }

        // Epilogue
#pragma unroll
        for (int mt = 0; mt < 4; ++mt) {
            int gr0 = m0 + warpM * 64 + mt * 16 + (L >> 2);
            int gr1 = gr0 + 8;
            float sc0 = 1.f, sc1 = 1.f;
            if (rowcnt) {
                if (gr0 < M) sc0 = (float)rowcnt[gr0];
                if (gr1 < M) sc1 = (float)rowcnt[gr1];
            }
#pragma unroll
            for (int ns = 0; ns < 8; ++ns) {
                int c = warpN * 64 + ns * 8 + (L & 3) * 2;
                float b0 = bias ? bias[c]     : 0.f;
                float b1v = bias ? bias[c + 1] : 0.f;
                float* Cp = (c < 128) ? C0 : C1;
                int   cl  = c & 127;
                float v00 = acc[mt][ns][0] + sc0 * b0;
                float v01 = acc[mt][ns][1] + sc0 * b1v;
                float v10 = acc[mt][ns][2] + sc1 * b0;
                float v11 = acc[mt][ns][3] + sc1 * b1v;
                if (do_relu) {
                    v00 = fmaxf(v00, 0.f); v01 = fmaxf(v01, 0.f);
                    v10 = fmaxf(v10, 0.f); v11 = fmaxf(v11, 0.f);
                }
                if (gr0 < M) *(float2*)(Cp + (size_t)gr0 * 128 + cl) = make_float2(v00, v01);
                if (gr1 < M) *(float2*)(Cp + (size_t)gr1 * 128 + cl) = make_float2(v10, v11);
            }
        }
    }
}

// ---------------------------------------------------------------------------
__global__ void __launch_bounds__(256)
zero_kernel()
{
    int idx = blockIdx.x * blockDim.x + threadIdx.x;
    int stride = gridDim.x * blockDim.x;
    for (int i = idx; i < NODES; i += stride) g_cnt[i] = 0;
    if (idx == 0) g_novf = 0;
}

__global__ void __launch_bounds__(256)
bucket_kernel(const int* __restrict__ ei)
{
    int e = blockIdx.x * blockDim.x + threadIdx.x;
    if (e >= EDGES) return;
    int s = ei[e];
    int d = ei[EDGES + e];
    int slot = atomicAdd(&g_cnt[d], 1);
    if (slot < CAP) {
        g_bucket[(size_t)d * CAP + slot] = s;
    } else {
        int o = atomicAdd(&g_novf, 1);
        if (o < OVFMAX) g_ovf[o] = make_int2(s, d);
    }
}

__global__ void __launch_bounds__(256)
node_kernel()
{
    int d    = (blockIdx.x * blockDim.x + threadIdx.x) >> 5;
    int lane = threadIdx.x & 31;
    if (d >= NODES) return;

    int n = g_cnt[d];
    if (n > CAP) n = CAP;

    float4 p = ((const float4*)(g_P + (size_t)d * HID))[lane];
    float4 acc = make_float4(0.f, 0.f, 0.f, 0.f);
    const int* bkt = g_bucket + (size_t)d * CAP;
#pragma unroll 2
    for (int i = 0; i < n; ++i) {
        int s = __ldg(bkt + i);
        float4 q = ((const float4*)(g_Q + (size_t)s * HID))[lane];
        acc.x += fmaxf(p.x + q.x, 0.f);
        acc.y += fmaxf(p.y + q.y, 0.f);
        acc.z += fmaxf(p.z + q.z, 0.f);
        acc.w += fmaxf(p.w + q.w, 0.f);
    }
    ((float4*)(g_S + (size_t)d * HID))[lane] = acc;
}

__global__ void __launch_bounds__(256)
fixup_kernel()
{
    int total = g_novf;
    if (total > OVFMAX) total = OVFMAX;
    int gw   = (blockIdx.x * blockDim.x + threadIdx.x) >> 5;
    int nw   = (gridDim.x * blockDim.x) >> 5;
    int lane = threadIdx.x & 31;
    for (int j = gw; j < total; j += nw) {
        int2 e = g_ovf[j];
        float4 p = ((const float4*)(g_P + (size_t)e.y * HID))[lane];
        float4 q = ((const float4*)(g_Q + (size_t)e.x * HID))[lane];
        float4 r;
        r.x = fmaxf(p.x + q.x, 0.f);
        r.y = fmaxf(p.y + q.y, 0.f);
        r.z = fmaxf(p.z + q.z, 0.f);
        r.w = fmaxf(p.w + q.w, 0.f);
        float* dst = g_S + (size_t)e.y * HID + lane * 4;
        asm volatile("red.global.add.v4.f32 [%0], {%1, %2, %3, %4};"
                     :: "l"(dst), "f"(r.x), "f"(r.y), "f"(r.z), "f"(r.w)
                     : "memory");
    }
}

__global__ void __launch_bounds__(256)
out_kernel(const float* __restrict__ H2, const float* __restrict__ Wc,
           const float* __restrict__ bc, float* __restrict__ out)
{
    int gw   = (blockIdx.x * blockDim.x + threadIdx.x) >> 5;
    int lane = threadIdx.x & 31;
    if (gw >= NODES) return;

    float4 hv  = ((const float4*)(H2 + (size_t)gw * HID))[lane];
    float4 w01 = ((const float4*)Wc)[lane * 2];
    float4 w23 = ((const float4*)Wc)[lane * 2 + 1];

    float a0 = hv.x * w01.x + hv.y * w01.z + hv.z * w23.x + hv.w * w23.z;
    float a1 = hv.x * w01.y + hv.y * w01.w + hv.z * w23.y + hv.w * w23.w;
#pragma unroll
    for (int off = 16; off > 0; off >>= 1) {
        a0 += __shfl_xor_sync(0xffffffffu, a0, off);
        a1 += __shfl_xor_sync(0xffffffffu, a1, off);
    }
    if (lane == 0) {
        out[(size_t)gw * 2]     = a0 + bc[0];
        out[(size_t)gw * 2 + 1] = a1 + bc[1];
    }
}

// ---------------------------------------------------------------------------
extern "C" void kernel_launch(void* const* d_in, const int* in_sizes, int n_in,
                              void* d_out, int out_size)
{
    const float* x    = (const float*)d_in[0];
    const int*   ei   = (const int*)d_in[1];
    const float* W_in = (const float*)d_in[2];
    const float* b_in = (const float*)d_in[3];
    const float* W1   = (const float*)d_in[4];
    const float* b1   = (const float*)d_in[5];
    const float* W2   = (const float*)d_in[6];
    const float* b2   = (const float*)d_in[7];
    const float* Wc   = (const float*)d_in[8];
    const float* bc   = (const float*)d_in[9];
    float*       out  = (float*)d_out;

    void *ph, *pP, *pQ, *pS, *pcnt, *pWin, *pW1, *pW2, *pb256;
    cudaGetSymbolAddress(&ph,    g_h);
    cudaGetSymbolAddress(&pP,    g_P);
    cudaGetSymbolAddress(&pQ,    g_Q);
    cudaGetSymbolAddress(&pS,    g_S);
    cudaGetSymbolAddress(&pcnt,  g_cnt);
    cudaGetSymbolAddress(&pWin,  g_iWin);
    cudaGetSymbolAddress(&pW1,   g_iW1);
    cudaGetSymbolAddress(&pW2,   g_iW2);
    cudaGetSymbolAddress(&pb256, g_bias256);

    const int SMEM = 192 * 1024;   // MT*512 + NT*512 for both variants
    cudaFuncSetAttribute(mma_gemm<4, 2>,
                         cudaFuncAttributeMaxDynamicSharedMemorySize, SMEM);
    cudaFuncSetAttribute(mma_gemm<2, 4>,
                         cudaFuncAttributeMaxDynamicSharedMemorySize, SMEM);

    const int M = NODES;
    const int tiles256 = (M + 255) / 256;   // 196
    const int tiles128 = (M + 127) / 128;   // 391
    const int GRID = 148;

    prep_kernel<<<257, 256>>>(W_in, W1, W2, b1);
    zero_kernel<<<256, 256>>>();
    bucket_kernel<<<(EDGES + 255) / 256, 256>>>(ei);

    // 1) h = relu(x @ W_in + b_in)           [M256 x N128 tiles]
    mma_gemm<4, 2><<<GRID, 256, SMEM>>>(x, (const uint4*)pWin, b_in, nullptr,
                                        (float*)ph, nullptr, M, tiles256, 1);
    // 2) P|Q = h @ [W1a|W1b] (+[b1|0])       [M128 x N256 tiles]
    mma_gemm<2, 4><<<GRID, 256, SMEM>>>((const float*)ph, (const uint4*)pW1,
                                        (const float*)pb256, nullptr,
                                        (float*)pP, (float*)pQ, M, tiles128, 0);
    // 3) aggregation
    node_kernel<<<(NODES * 32 + 255) / 256, 256>>>();
    fixup_kernel<<<64, 256>>>();
    // 4) h2 = relu(S @ W2 + deg*b2)
    mma_gemm<4, 2><<<GRID, 256, SMEM>>>((const float*)pS, (const uint4*)pW2, b2,
                                        (const int*)pcnt, (float*)ph, nullptr,
                                        M, tiles256, 1);
    // 5) out = h2 @ Wc + bc
    out_kernel<<<(NODES * 32 + 255) / 256, 256>>>((const float*)ph, Wc, bc, out);
}

// round 7
// speedup vs baseline: 1.8635x; 1.0167x over previous
#include <cuda_runtime.h>
#include <cuda_bf16.h>
#include <cstdint>

#define NODES 50000
#define EDGES 800000
#define HID   128
#define CAP   128
#define OVFMAX 65536

// ---------------------------------------------------------------------------
// Device-global scratch (no allocations allowed)
// ---------------------------------------------------------------------------
__device__ float g_h[(size_t)NODES * HID];
__device__ float g_P[(size_t)NODES * HID];
__device__ float g_Q[(size_t)NODES * HID];
__device__ float g_S[(size_t)NODES * HID];
__device__ int   g_cnt[NODES];
__device__ int   g_bucket[(size_t)NODES * CAP];
__device__ int2  g_ovf[OVFMAX];
__device__ int   g_novf;

// Pre-transposed, bf16 hi/lo split, smem-swizzled weight images (N=128, K=128).
// Layout: hi block (32 KB) then lo block. Element (n,k) at byte
// off = n*256 + ((k>>6)<<7) + (((k&63)<<1) ^ ((n&7)<<4)).
__device__ uint4 g_iWin[4096];
__device__ uint4 g_iW1a[4096];
__device__ uint4 g_iW1b[4096];
__device__ uint4 g_iW2 [4096];

__device__ __forceinline__ uint32_t smem_u32(const void* p) {
    uint32_t a;
    asm("{ .reg .u64 t; cvta.to.shared.u64 t, %1; cvt.u32.u64 %0, t; }"
        : "=r"(a) : "l"(p));
    return a;
}
__device__ __forceinline__ unsigned packbf(float x, float y) {
    __nv_bfloat162 t = __floats2bfloat162_rn(x, y);
    return *reinterpret_cast<unsigned*>(&t);
}
__device__ __forceinline__ void ldsm4(unsigned* r, uint32_t addr) {
    asm volatile("ldmatrix.sync.aligned.m8n8.x4.shared.b16 {%0,%1,%2,%3}, [%4];"
                 : "=r"(r[0]), "=r"(r[1]), "=r"(r[2]), "=r"(r[3]) : "r"(addr));
}
__device__ __forceinline__ void mma16816(float* d, const unsigned* a,
                                         unsigned b0, unsigned b1) {
    asm volatile(
        "mma.sync.aligned.m16n8k16.row.col.f32.bf16.bf16.f32 "
        "{%0,%1,%2,%3},{%4,%5,%6,%7},{%8,%9},{%0,%1,%2,%3};"
        : "+f"(d[0]), "+f"(d[1]), "+f"(d[2]), "+f"(d[3])
        : "r"(a[0]), "r"(a[1]), "r"(a[2]), "r"(a[3]), "r"(b0), "r"(b1));
}

// ---------------------------------------------------------------------------
// Prep: build 4 weight images (transpose + bf16 hi/lo split + swizzle)
// ---------------------------------------------------------------------------
__device__ __forceinline__ void img_write(uint4* img, int n, int k, float v) {
    __nv_bfloat16 hi = __float2bfloat16(v);
    float hf = __bfloat162float(hi);
    __nv_bfloat16 lo = __float2bfloat16(v - hf);
    uint32_t off = (uint32_t)n * 256 + ((k >> 6) << 7) +
                   ((((k & 63) << 1)) ^ ((n & 7) << 4));
    __nv_bfloat16* p = (__nv_bfloat16*)img;
    p[off >> 1]               = hi;
    p[128 * 128 + (off >> 1)] = lo;   // lo block 32 KB after hi
}

__global__ void __launch_bounds__(256)
prep_kernel(const float* __restrict__ W_in, const float* __restrict__ W1,
            const float* __restrict__ W2)
{
    int idx = blockIdx.x * blockDim.x + threadIdx.x;
    int n = (idx >> 7) & 127, k = idx & 127;
    if (idx < 16384) {
        img_write(g_iWin, n, k, W_in[k * 128 + n]);
    } else if (idx < 32768) {
        img_write(g_iW1a, n, k, W1[k * 128 + n]);
    } else if (idx < 49152) {
        img_write(g_iW1b, n, k, W1[(128 + k) * 128 + n]);
    } else if (idx < 65536) {
        img_write(g_iW2, n, k, W2[k * 128 + n]);
    }
}

// ---------------------------------------------------------------------------
// HMMA GEMM: C[M,128] = act( A[M,128] @ W + rowscale * bias )
// Persistent grid; 512 threads = 16 warps; CTA tile 128x128; warp tile 32x32.
// 3-term bf16 split: Ah*Wh + Al*Wh + Ah*Wl. W staged in smem once per CTA.
// smem: [A_hi 32K][A_lo 32K][W_hi 32K][W_lo 32K] = 128 KB.
// ---------------------------------------------------------------------------
__global__ void __launch_bounds__(512, 1)
mma_gemm(const float* __restrict__ A, const uint4* __restrict__ Wimg,
         const float* __restrict__ bias, const int* __restrict__ rowcnt,
         float* __restrict__ C, int M, int ntiles, int do_relu)
{
    extern __shared__ char smem[];
    const uint32_t sb  = smem_u32(smem);
    const uint32_t sAh = sb;
    const uint32_t sAl = sb + 32768;
    const uint32_t sWh = sb + 65536;
    const uint32_t sWl = sb + 98304;

    const int tid = threadIdx.x;
    const int wid = tid >> 5;
    const int L   = tid & 31;
    const int warpM = wid >> 2;   // 0..3
    const int warpN = wid & 3;    // 0..3

    // Stage W image once (hi+lo = 64 KB = 4096 uint4)
    {
        uint4* dst = (uint4*)(smem + 65536);
        for (int i = tid; i < 4096; i += 512) dst[i] = Wimg[i];
    }

    const int fi   = L & 15;
    const int fswz = (fi & 7) << 4;
    const int fk8  = (L >> 4) * 8;

    // A staging: 4 threads per row, 8 float4 each
    const int sr = tid >> 2;
    const int sq = tid & 3;

    for (int tile = blockIdx.x; tile < ntiles; tile += gridDim.x) {
        const int m0 = tile * 128;
        __syncthreads();   // prior-iter smem reads done (also orders W copy)

        {
            const int gr = m0 + sr;
            const float4* Ar = (const float4*)A + (size_t)gr * 32 + sq * 8;
#pragma unroll
            for (int j = 0; j < 8; ++j) {
                float4 v = make_float4(0.f, 0.f, 0.f, 0.f);
                if (gr < M) v = Ar[j];
                float hx = __bfloat162float(__float2bfloat16(v.x));
                float hy = __bfloat162float(__float2bfloat16(v.y));
                float hz = __bfloat162float(__float2bfloat16(v.z));
                float hw = __bfloat162float(__float2bfloat16(v.w));
                uint2 hh = make_uint2(packbf(v.x, v.y), packbf(v.z, v.w));
                uint2 ll = make_uint2(packbf(v.x - hx, v.y - hy),
                                      packbf(v.z - hz, v.w - hw));
                int k = (sq * 8 + j) * 4;
                uint32_t off = (uint32_t)sr * 256 + ((k >> 6) << 7) +
                               ((((k & 63) << 1)) ^ ((sr & 7) << 4));
                *(uint2*)(smem + off)         = hh;
                *(uint2*)(smem + 32768 + off) = ll;
            }
        }
        __syncthreads();

        float acc[2][4][4];
#pragma unroll
        for (int mt = 0; mt < 2; ++mt)
#pragma unroll
            for (int ns = 0; ns < 4; ++ns)
#pragma unroll
                for (int e = 0; e < 4; ++e) acc[mt][ns][e] = 0.f;

#pragma unroll
        for (int t = 0; t < 3; ++t) {
            const uint32_t ab = (t == 1) ? sAl : sAh;
            const uint32_t wb = (t == 2) ? sWl : sWh;
#pragma unroll
            for (int ks = 0; ks < 8; ++ks) {
                const int k8 = ks * 16 + fk8;
                const uint32_t koff = ((k8 >> 6) << 7) + (((k8 & 63) << 1) ^ fswz);
                unsigned bt[2][4], a[2][4];
#pragma unroll
                for (int nt = 0; nt < 2; ++nt) {
                    int n = warpN * 32 + nt * 16 + fi;
                    ldsm4(bt[nt], wb + (uint32_t)n * 256 + koff);
                }
#pragma unroll
                for (int mt = 0; mt < 2; ++mt) {
                    int r = warpM * 32 + mt * 16 + fi;
                    ldsm4(a[mt], ab + (uint32_t)r * 256 + koff);
                }
#pragma unroll
                for (int mt = 0; mt < 2; ++mt)
#pragma unroll
                    for (int nt = 0; nt < 2; ++nt) {
                        mma16816(acc[mt][nt * 2],     a[mt], bt[nt][0], bt[nt][2]);
                        mma16816(acc[mt][nt * 2 + 1], a[mt], bt[nt][1], bt[nt][3]);
                    }
            }
        }

        // Epilogue (registers -> gmem; no smem)
#pragma unroll
        for (int mt = 0; mt < 2; ++mt) {
            int gr0 = m0 + warpM * 32 + mt * 16 + (L >> 2);
            int gr1 = gr0 + 8;
            float sc0 = 1.f, sc1 = 1.f;
            if (rowcnt) {
                if (gr0 < M) sc0 = (float)rowcnt[gr0];
                if (gr1 < M) sc1 = (float)rowcnt[gr1];
            }
#pragma unroll
            for (int ns = 0; ns < 4; ++ns) {
                int c = warpN * 32 + ns * 8 + (L & 3) * 2;
                float b0 = bias ? bias[c]     : 0.f;
                float b1 = bias ? bias[c + 1] : 0.f;
                float v00 = acc[mt][ns][0] + sc0 * b0;
                float v01 = acc[mt][ns][1] + sc0 * b1;
                float v10 = acc[mt][ns][2] + sc1 * b0;
                float v11 = acc[mt][ns][3] + sc1 * b1;
                if (do_relu) {
                    v00 = fmaxf(v00, 0.f); v01 = fmaxf(v01, 0.f);
                    v10 = fmaxf(v10, 0.f); v11 = fmaxf(v11, 0.f);
                }
                if (gr0 < M) *(float2*)(C + (size_t)gr0 * 128 + c) = make_float2(v00, v01);
                if (gr1 < M) *(float2*)(C + (size_t)gr1 * 128 + c) = make_float2(v10, v11);
            }
        }
    }
}

// ---------------------------------------------------------------------------
__global__ void __launch_bounds__(256)
zero_kernel()
{
    int idx = blockIdx.x * blockDim.x + threadIdx.x;
    int stride = gridDim.x * blockDim.x;
    for (int i = idx; i < NODES; i += stride) g_cnt[i] = 0;
    if (idx == 0) g_novf = 0;
}

__global__ void __launch_bounds__(256)
bucket_kernel(const int* __restrict__ ei)
{
    int e = blockIdx.x * blockDim.x + threadIdx.x;
    if (e >= EDGES) return;
    int s = ei[e];
    int d = ei[EDGES + e];
    int slot = atomicAdd(&g_cnt[d], 1);
    if (slot < CAP) {
        g_bucket[(size_t)d * CAP + slot] = s;
    } else {
        int o = atomicAdd(&g_novf, 1);
        if (o < OVFMAX) g_ovf[o] = make_int2(s, d);
    }
}

__global__ void __launch_bounds__(256)
node_kernel()
{
    int d    = (blockIdx.x * blockDim.x + threadIdx.x) >> 5;
    int lane = threadIdx.x & 31;
    if (d >= NODES) return;

    int n = g_cnt[d];
    if (n > CAP) n = CAP;

    float4 p = ((const float4*)(g_P + (size_t)d * HID))[lane];
    float4 acc = make_float4(0.f, 0.f, 0.f, 0.f);
    const int* bkt = g_bucket + (size_t)d * CAP;
#pragma unroll 2
    for (int i = 0; i < n; ++i) {
        int s = __ldg(bkt + i);
        float4 q = ((const float4*)(g_Q + (size_t)s * HID))[lane];
        acc.x += fmaxf(p.x + q.x, 0.f);
        acc.y += fmaxf(p.y + q.y, 0.f);
        acc.z += fmaxf(p.z + q.z, 0.f);
        acc.w += fmaxf(p.w + q.w, 0.f);
    }
    ((float4*)(g_S + (size_t)d * HID))[lane] = acc;
}

__global__ void __launch_bounds__(256)
fixup_kernel()
{
    int total = g_novf;
    if (total > OVFMAX) total = OVFMAX;
    int gw   = (blockIdx.x * blockDim.x + threadIdx.x) >> 5;
    int nw   = (gridDim.x * blockDim.x) >> 5;
    int lane = threadIdx.x & 31;
    for (int j = gw; j < total; j += nw) {
        int2 e = g_ovf[j];
        float4 p = ((const float4*)(g_P + (size_t)e.y * HID))[lane];
        float4 q = ((const float4*)(g_Q + (size_t)e.x * HID))[lane];
        float4 r;
        r.x = fmaxf(p.x + q.x, 0.f);
        r.y = fmaxf(p.y + q.y, 0.f);
        r.z = fmaxf(p.z + q.z, 0.f);
        r.w = fmaxf(p.w + q.w, 0.f);
        float* dst = g_S + (size_t)e.y * HID + lane * 4;
        asm volatile("red.global.add.v4.f32 [%0], {%1, %2, %3, %4};"
                     :: "l"(dst), "f"(r.x), "f"(r.y), "f"(r.z), "f"(r.w)
                     : "memory");
    }
}

__global__ void __launch_bounds__(256)
out_kernel(const float* __restrict__ H2, const float* __restrict__ Wc,
           const float* __restrict__ bc, float* __restrict__ out)
{
    int gw   = (blockIdx.x * blockDim.x + threadIdx.x) >> 5;
    int lane = threadIdx.x & 31;
    if (gw >= NODES) return;

    float4 hv  = ((const float4*)(H2 + (size_t)gw * HID))[lane];
    float4 w01 = ((const float4*)Wc)[lane * 2];
    float4 w23 = ((const float4*)Wc)[lane * 2 + 1];

    float a0 = hv.x * w01.x + hv.y * w01.z + hv.z * w23.x + hv.w * w23.z;
    float a1 = hv.x * w01.y + hv.y * w01.w + hv.z * w23.y + hv.w * w23.w;
#pragma unroll
    for (int off = 16; off > 0; off >>= 1) {
        a0 += __shfl_xor_sync(0xffffffffu, a0, off);
        a1 += __shfl_xor_sync(0xffffffffu, a1, off);
    }
    if (lane == 0) {
        out[(size_t)gw * 2]     = a0 + bc[0];
        out[(size_t)gw * 2 + 1] = a1 + bc[1];
    }
}

// ---------------------------------------------------------------------------
extern "C" void kernel_launch(void* const* d_in, const int* in_sizes, int n_in,
                              void* d_out, int out_size)
{
    const float* x    = (const float*)d_in[0];
    const int*   ei   = (const int*)d_in[1];
    const float* W_in = (const float*)d_in[2];
    const float* b_in = (const float*)d_in[3];
    const float* W1   = (const float*)d_in[4];
    const float* b1   = (const float*)d_in[5];
    const float* W2   = (const float*)d_in[6];
    const float* b2   = (const float*)d_in[7];
    const float* Wc   = (const float*)d_in[8];
    const float* bc   = (const float*)d_in[9];
    float*       out  = (float*)d_out;

    void *ph, *pP, *pQ, *pS, *pcnt, *pWin, *pW1a, *pW1b, *pW2;
    cudaGetSymbolAddress(&ph,   g_h);
    cudaGetSymbolAddress(&pP,   g_P);
    cudaGetSymbolAddress(&pQ,   g_Q);
    cudaGetSymbolAddress(&pS,   g_S);
    cudaGetSymbolAddress(&pcnt, g_cnt);
    cudaGetSymbolAddress(&pWin, g_iWin);
    cudaGetSymbolAddress(&pW1a, g_iW1a);
    cudaGetSymbolAddress(&pW1b, g_iW1b);
    cudaGetSymbolAddress(&pW2,  g_iW2);

    const int SMEM = 128 * 1024;
    cudaFuncSetAttribute(mma_gemm, cudaFuncAttributeMaxDynamicSharedMemorySize,
                         SMEM);

    const int M = NODES;
    const int tiles = (M + 127) / 128;   // 391
    const int GRID = 148;

    prep_kernel<<<256, 256>>>(W_in, W1, W2);
    zero_kernel<<<256, 256>>>();
    bucket_kernel<<<(EDGES + 255) / 256, 256>>>(ei);

    // 1) h = relu(x @ W_in + b_in)
    mma_gemm<<<GRID, 512, SMEM>>>(x, (const uint4*)pWin, b_in, nullptr,
                                  (float*)ph, M, tiles, 1);
    // 2) P = h @ W1a + b1
    mma_gemm<<<GRID, 512, SMEM>>>((const float*)ph, (const uint4*)pW1a, b1,
                                  nullptr, (float*)pP, M, tiles, 0);
    // 3) Q = h @ W1b
    mma_gemm<<<GRID, 512, SMEM>>>((const float*)ph, (const uint4*)pW1b, nullptr,
                                  nullptr, (float*)pQ, M, tiles, 0);
    // 4) aggregation
    node_kernel<<<(NODES * 32 + 255) / 256, 256>>>();
    fixup_kernel<<<64, 256>>>();
    // 5) h2 = relu(S @ W2 + deg*b2)
    mma_gemm<<<GRID, 512, SMEM>>>((const float*)pS, (const uint4*)pW2, b2,
                                  (const int*)pcnt, (float*)ph, M, tiles, 1);
    // 6) out = h2 @ Wc + bc
    out_kernel<<<(NODES * 32 + 255) / 256, 256>>>((const float*)ph, Wc, bc, out);
}

// round 8
// speedup vs baseline: 2.1876x; 1.1739x over previous
#include <cuda_runtime.h>
#include <cuda_bf16.h>
#include <cstdint>

#define NODES 50000
#define EDGES 800000
#define HID   128
#define CAP   128
#define OVFMAX 65536
#define NTILES 391            // ceil(50000/128)

// ---------------------------------------------------------------------------
// Device-global scratch (no allocations allowed)
// ---------------------------------------------------------------------------
__device__ float g_h2[(size_t)NODES * HID];      // h2 (S@W2 result)
__device__ float g_P[(size_t)NODES * HID];
__device__ float g_Q[(size_t)NODES * HID];
__device__ int   g_cnt[NODES];
__device__ int   g_bucket[(size_t)NODES * CAP];
__device__ int2  g_ovf[OVFMAX];
__device__ int   g_novf;

// bf16 hi/lo "image" arrays: per 128-row tile, 32 KB contiguous, element (r,k)
// at byte off = r*256 + ((k>>6)<<7) + (((k&63)<<1) ^ ((r&7)<<4)).
__device__ uint4 g_hHi[(size_t)NTILES * 2048];   // 12.8 MB
__device__ uint4 g_hLo[(size_t)NTILES * 2048];
__device__ uint4 g_sHi[(size_t)NTILES * 2048];
__device__ uint4 g_sLo[(size_t)NTILES * 2048];

// Weight images (transposed, hi block 32KB then lo block 32KB)
__device__ uint4 g_iWin[4096];
__device__ uint4 g_iW1a[4096];
__device__ uint4 g_iW1b[4096];
__device__ uint4 g_iW2 [4096];

// ---------------------------------------------------------------------------
__device__ __forceinline__ uint32_t smem_u32(const void* p) {
    uint32_t a;
    asm("{ .reg .u64 t; cvta.to.shared.u64 t, %1; cvt.u32.u64 %0, t; }"
        : "=r"(a) : "l"(p));
    return a;
}
__device__ __forceinline__ unsigned packbf(float x, float y) {
    __nv_bfloat162 t = __floats2bfloat162_rn(x, y);
    return *reinterpret_cast<unsigned*>(&t);
}
__device__ __forceinline__ void ldsm4(unsigned* r, uint32_t addr) {
    asm volatile("ldmatrix.sync.aligned.m8n8.x4.shared.b16 {%0,%1,%2,%3}, [%4];"
                 : "=r"(r[0]), "=r"(r[1]), "=r"(r[2]), "=r"(r[3]) : "r"(addr));
}
__device__ __forceinline__ void mma16816(float* d, const unsigned* a,
                                         unsigned b0, unsigned b1) {
    asm volatile(
        "mma.sync.aligned.m16n8k16.row.col.f32.bf16.bf16.f32 "
        "{%0,%1,%2,%3},{%4,%5,%6,%7},{%8,%9},{%0,%1,%2,%3};"
        : "+f"(d[0]), "+f"(d[1]), "+f"(d[2]), "+f"(d[3])
        : "r"(a[0]), "r"(a[1]), "r"(a[2]), "r"(a[3]), "r"(b0), "r"(b1));
}
__device__ __forceinline__ void cpa16(uint32_t dst, const void* src) {
    asm volatile("cp.async.cg.shared.global [%0], [%1], 16;"
                 :: "r"(dst), "l"(src));
}
#define CP_COMMIT() asm volatile("cp.async.commit_group;" ::: "memory")
#define CP_WAIT0()  asm volatile("cp.async.wait_group 0;" ::: "memory")

__device__ __forceinline__ uint32_t img_off(int r, int k) {
    return (uint32_t)r * 256 + ((k >> 6) << 7) + ((((k & 63) << 1)) ^ ((r & 7) << 4));
}

// ---------------------------------------------------------------------------
// Prep: weight images
// ---------------------------------------------------------------------------
__device__ __forceinline__ void img_write(uint4* img, int n, int k, float v) {
    __nv_bfloat16 hi = __float2bfloat16(v);
    float hf = __bfloat162float(hi);
    __nv_bfloat16 lo = __float2bfloat16(v - hf);
    uint32_t off = img_off(n, k);
    __nv_bfloat16* p = (__nv_bfloat16*)img;
    p[off >> 1]               = hi;
    p[128 * 128 + (off >> 1)] = lo;
}

__global__ void __launch_bounds__(256)
prep_kernel(const float* __restrict__ W_in, const float* __restrict__ W1,
            const float* __restrict__ W2)
{
    int idx = blockIdx.x * blockDim.x + threadIdx.x;
    int n = (idx >> 7) & 127, k = idx & 127;
    if (idx < 16384) {
        img_write(g_iWin, n, k, W_in[k * 128 + n]);
    } else if (idx < 32768) {
        img_write(g_iW1a, n, k, W1[k * 128 + n]);
    } else if (idx < 49152) {
        img_write(g_iW1b, n, k, W1[(128 + k) * 128 + n]);
    } else if (idx < 65536) {
        img_write(g_iW2, n, k, W2[k * 128 + n]);
    }
}

// ---------------------------------------------------------------------------
// Shared mainloop: 3-term bf16 split over one 128x128 tile.
// ---------------------------------------------------------------------------
__device__ __forceinline__ void tile_mainloop(
    float acc[2][4][4], uint32_t sAh, uint32_t sAl, uint32_t sWh, uint32_t sWl,
    int warpM, int warpN, int fi, int fswz, int fk8)
{
#pragma unroll
    for (int mt = 0; mt < 2; ++mt)
#pragma unroll
        for (int ns = 0; ns < 4; ++ns)
#pragma unroll
            for (int e = 0; e < 4; ++e) acc[mt][ns][e] = 0.f;

#pragma unroll
    for (int t = 0; t < 3; ++t) {
        const uint32_t ab = (t == 1) ? sAl : sAh;
        const uint32_t wb = (t == 2) ? sWl : sWh;
#pragma unroll
        for (int ks = 0; ks < 8; ++ks) {
            const int k8 = ks * 16 + fk8;
            const uint32_t koff = ((k8 >> 6) << 7) + (((k8 & 63) << 1) ^ fswz);
            unsigned bt[2][4], a[2][4];
#pragma unroll
            for (int nt = 0; nt < 2; ++nt)
                ldsm4(bt[nt], wb + (uint32_t)(warpN * 32 + nt * 16 + fi) * 256 + koff);
#pragma unroll
            for (int mt = 0; mt < 2; ++mt)
                ldsm4(a[mt], ab + (uint32_t)(warpM * 32 + mt * 16 + fi) * 256 + koff);
#pragma unroll
            for (int mt = 0; mt < 2; ++mt)
#pragma unroll
                for (int nt = 0; nt < 2; ++nt) {
                    mma16816(acc[mt][nt * 2],     a[mt], bt[nt][0], bt[nt][2]);
                    mma16816(acc[mt][nt * 2 + 1], a[mt], bt[nt][1], bt[nt][3]);
                }
        }
    }
}

// ---------------------------------------------------------------------------
// GEMM-A: x (fp32) -> h images (relu(x@Win + b_in), bf16 hi/lo split)
// 512 thr, CTA tile 128x128, warp tile 32x32; convert-staging as R7.
// smem: [A_hi 32K][A_lo 32K][W_hi 32K][W_lo 32K] = 128 KB.
// ---------------------------------------------------------------------------
__global__ void __launch_bounds__(512, 1)
gemm_a(const float* __restrict__ A, const uint4* __restrict__ Wimg,
       const float* __restrict__ bias, uint4* __restrict__ outHi,
       uint4* __restrict__ outLo, int M, int ntiles)
{
    extern __shared__ char smem[];
    const uint32_t sb  = smem_u32(smem);
    const uint32_t sAh = sb, sAl = sb + 32768, sWh = sb + 65536, sWl = sb + 98304;

    const int tid = threadIdx.x;
    const int wid = tid >> 5;
    const int L   = tid & 31;
    const int warpM = wid >> 2, warpN = wid & 3;

    {
        uint4* dst = (uint4*)(smem + 65536);
        for (int i = tid; i < 4096; i += 512) dst[i] = Wimg[i];
    }

    const int fi = L & 15, fswz = (fi & 7) << 4, fk8 = (L >> 4) * 8;
    const int sr = tid >> 2, sq = tid & 3;

    for (int tile = blockIdx.x; tile < ntiles; tile += gridDim.x) {
        const int m0 = tile * 128;
        __syncthreads();
        {
            const int gr = m0 + sr;
            const float4* Ar = (const float4*)A + (size_t)gr * 32 + sq * 8;
#pragma unroll
            for (int j = 0; j < 8; ++j) {
                float4 v = make_float4(0.f, 0.f, 0.f, 0.f);
                if (gr < M) v = Ar[j];
                float hx = __bfloat162float(__float2bfloat16(v.x));
                float hy = __bfloat162float(__float2bfloat16(v.y));
                float hz = __bfloat162float(__float2bfloat16(v.z));
                float hw = __bfloat162float(__float2bfloat16(v.w));
                uint2 hh = make_uint2(packbf(v.x, v.y), packbf(v.z, v.w));
                uint2 ll = make_uint2(packbf(v.x - hx, v.y - hy),
                                      packbf(v.z - hz, v.w - hw));
                uint32_t off = img_off(sr, (sq * 8 + j) * 4);
                *(uint2*)(smem + off)         = hh;
                *(uint2*)(smem + 32768 + off) = ll;
            }
        }
        __syncthreads();

        float acc[2][4][4];
        tile_mainloop(acc, sAh, sAl, sWh, sWl, warpM, warpN, fi, fswz, fk8);

        // Epilogue: relu, split, write hi/lo images
        char* hB = (char*)outHi + (size_t)tile * 32768;
        char* lB = (char*)outLo + (size_t)tile * 32768;
#pragma unroll
        for (int mt = 0; mt < 2; ++mt) {
            int r0 = warpM * 32 + mt * 16 + (L >> 2);
            int r1 = r0 + 8;
            int gr0 = m0 + r0, gr1 = m0 + r1;
#pragma unroll
            for (int ns = 0; ns < 4; ++ns) {
                int c = warpN * 32 + ns * 8 + (L & 3) * 2;
                float b0 = bias[c], b1 = bias[c + 1];
                float v00 = fmaxf(acc[mt][ns][0] + b0, 0.f);
                float v01 = fmaxf(acc[mt][ns][1] + b1, 0.f);
                float v10 = fmaxf(acc[mt][ns][2] + b0, 0.f);
                float v11 = fmaxf(acc[mt][ns][3] + b1, 0.f);
                if (gr0 < M) {
                    uint32_t off = img_off(r0, c);
                    float h0 = __bfloat162float(__float2bfloat16(v00));
                    float h1 = __bfloat162float(__float2bfloat16(v01));
                    *(unsigned*)(hB + off) = packbf(v00, v01);
                    *(unsigned*)(lB + off) = packbf(v00 - h0, v01 - h1);
                }
                if (gr1 < M) {
                    uint32_t off = img_off(r1, c);
                    float h0 = __bfloat162float(__float2bfloat16(v10));
                    float h1 = __bfloat162float(__float2bfloat16(v11));
                    *(unsigned*)(hB + off) = packbf(v10, v11);
                    *(unsigned*)(lB + off) = packbf(v10 - h0, v11 - h1);
                }
            }
        }
    }
}

// ---------------------------------------------------------------------------
// GEMM-B: image input (bf16 hi/lo), cp.async double-buffered pipeline.
// smem: [A0 64K][A1 64K][W 64K] = 192 KB.
// C = act( img @ W + rowscale*bias ), fp32 output.
// ---------------------------------------------------------------------------
__global__ void __launch_bounds__(512, 1)
gemm_b(const uint4* __restrict__ hiImg, const uint4* __restrict__ loImg,
       const uint4* __restrict__ Wimg, const float* __restrict__ bias,
       const int* __restrict__ rowcnt, float* __restrict__ C,
       int M, int ntiles, int do_relu)
{
    extern __shared__ char smem[];
    const uint32_t sb  = smem_u32(smem);
    const uint32_t sW  = sb + 131072;

    const int tid = threadIdx.x;
    const int wid = tid >> 5;
    const int L   = tid & 31;
    const int warpM = wid >> 2, warpN = wid & 3;
    const int fi = L & 15, fswz = (fi & 7) << 4, fk8 = (L >> 4) * 8;

    // Prologue: async-copy W image + first tile
    for (int i = tid; i < 4096; i += 512) cpa16(sW + i * 16, Wimg + i);
    {
        int t0 = blockIdx.x;
        const uint4* sH = hiImg + (size_t)t0 * 2048;
        const uint4* sL = loImg + (size_t)t0 * 2048;
        for (int i = tid; i < 2048; i += 512) {
            cpa16(sb + i * 16, sH + i);
            cpa16(sb + 32768 + i * 16, sL + i);
        }
    }
    CP_COMMIT();

    int cur = 0;
    for (int tile = blockIdx.x; tile < ntiles; tile += gridDim.x) {
        CP_WAIT0();
        __syncthreads();

        int nxt = tile + gridDim.x;
        if (nxt < ntiles) {
            uint32_t dst = sb + (cur ^ 1) * 65536;
            const uint4* sH = hiImg + (size_t)nxt * 2048;
            const uint4* sL = loImg + (size_t)nxt * 2048;
            for (int i = tid; i < 2048; i += 512) {
                cpa16(dst + i * 16, sH + i);
                cpa16(dst + 32768 + i * 16, sL + i);
            }
        }
        CP_COMMIT();

        const uint32_t sAh = sb + cur * 65536;
        float acc[2][4][4];
        tile_mainloop(acc, sAh, sAh + 32768, sW, sW + 32768,
                      warpM, warpN, fi, fswz, fk8);

        const int m0 = tile * 128;
#pragma unroll
        for (int mt = 0; mt < 2; ++mt) {
            int gr0 = m0 + warpM * 32 + mt * 16 + (L >> 2);
            int gr1 = gr0 + 8;
            float sc0 = 1.f, sc1 = 1.f;
            if (rowcnt) {
                if (gr0 < M) sc0 = (float)rowcnt[gr0];
                if (gr1 < M) sc1 = (float)rowcnt[gr1];
            }
#pragma unroll
            for (int ns = 0; ns < 4; ++ns) {
                int c = warpN * 32 + ns * 8 + (L & 3) * 2;
                float b0 = bias ? bias[c]     : 0.f;
                float b1 = bias ? bias[c + 1] : 0.f;
                float v00 = acc[mt][ns][0] + sc0 * b0;
                float v01 = acc[mt][ns][1] + sc0 * b1;
                float v10 = acc[mt][ns][2] + sc1 * b0;
                float v11 = acc[mt][ns][3] + sc1 * b1;
                if (do_relu) {
                    v00 = fmaxf(v00, 0.f); v01 = fmaxf(v01, 0.f);
                    v10 = fmaxf(v10, 0.f); v11 = fmaxf(v11, 0.f);
                }
                if (gr0 < M) *(float2*)(C + (size_t)gr0 * 128 + c) = make_float2(v00, v01);
                if (gr1 < M) *(float2*)(C + (size_t)gr1 * 128 + c) = make_float2(v10, v11);
            }
        }
        cur ^= 1;
    }
}

// ---------------------------------------------------------------------------
__global__ void __launch_bounds__(256)
zero_kernel()
{
    int idx = blockIdx.x * blockDim.x + threadIdx.x;
    int stride = gridDim.x * blockDim.x;
    for (int i = idx; i < NODES; i += stride) g_cnt[i] = 0;
    if (idx == 0) g_novf = 0;
}

__global__ void __launch_bounds__(256)
bucket_kernel(const int* __restrict__ ei)
{
    int e = blockIdx.x * blockDim.x + threadIdx.x;
    if (e >= EDGES) return;
    int s = ei[e];
    int d = ei[EDGES + e];
    int slot = atomicAdd(&g_cnt[d], 1);
    if (slot < CAP) {
        g_bucket[(size_t)d * CAP + slot] = s;
    } else {
        int o = atomicAdd(&g_novf, 1);
        if (o < OVFMAX) g_ovf[o] = make_int2(s, d);
    }
}

// Warp per node: S[d] = sum relu(P[d]+Q[src]); write S as bf16 hi/lo images.
__global__ void __launch_bounds__(256)
node_kernel()
{
    int d    = (blockIdx.x * blockDim.x + threadIdx.x) >> 5;
    int lane = threadIdx.x & 31;
    if (d >= NODES) return;

    int n = g_cnt[d];
    if (n > CAP) n = CAP;

    float4 p = ((const float4*)(g_P + (size_t)d * HID))[lane];
    float4 acc = make_float4(0.f, 0.f, 0.f, 0.f);
    const int* bkt = g_bucket + (size_t)d * CAP;
#pragma unroll 2
    for (int i = 0; i < n; ++i) {
        int s = __ldg(bkt + i);
        float4 q = ((const float4*)(g_Q + (size_t)s * HID))[lane];
        acc.x += fmaxf(p.x + q.x, 0.f);
        acc.y += fmaxf(p.y + q.y, 0.f);
        acc.z += fmaxf(p.z + q.z, 0.f);
        acc.w += fmaxf(p.w + q.w, 0.f);
    }
    int r = d & 127;
    uint32_t off = img_off(r, lane * 4);
    char* hB = (char*)g_sHi + (size_t)(d >> 7) * 32768;
    char* lB = (char*)g_sLo + (size_t)(d >> 7) * 32768;
    float hx = __bfloat162float(__float2bfloat16(acc.x));
    float hy = __bfloat162float(__float2bfloat16(acc.y));
    float hz = __bfloat162float(__float2bfloat16(acc.z));
    float hw = __bfloat162float(__float2bfloat16(acc.w));
    *(uint2*)(hB + off) = make_uint2(packbf(acc.x, acc.y), packbf(acc.z, acc.w));
    *(uint2*)(lB + off) = make_uint2(packbf(acc.x - hx, acc.y - hy),
                                     packbf(acc.z - hz, acc.w - hw));
}

// Serial overflow fixup (single warp; expected empty). RMW on S images.
__global__ void __launch_bounds__(32)
fixup_kernel()
{
    int total = g_novf;
    if (total > OVFMAX) total = OVFMAX;
    int lane = threadIdx.x;
    for (int j = 0; j < total; ++j) {
        int2 e = g_ovf[j];
        float4 p = ((const float4*)(g_P + (size_t)e.y * HID))[lane];
        float4 q = ((const float4*)(g_Q + (size_t)e.x * HID))[lane];
        int r = e.y & 127;
        uint32_t off = img_off(r, lane * 4);
        char* hB = (char*)g_sHi + (size_t)(e.y >> 7) * 32768;
        char* lB = (char*)g_sLo + (size_t)(e.y >> 7) * 32768;
        uint2 hh = *(uint2*)(hB + off);
        uint2 ll = *(uint2*)(lB + off);
        __nv_bfloat162 h0 = *(__nv_bfloat162*)&hh.x, h1 = *(__nv_bfloat162*)&hh.y;
        __nv_bfloat162 l0 = *(__nv_bfloat162*)&ll.x, l1 = *(__nv_bfloat162*)&ll.y;
        float vx = __bfloat162float(h0.x) + __bfloat162float(l0.x) + fmaxf(p.x + q.x, 0.f);
        float vy = __bfloat162float(h0.y) + __bfloat162float(l0.y) + fmaxf(p.y + q.y, 0.f);
        float vz = __bfloat162float(h1.x) + __bfloat162float(l1.x) + fmaxf(p.z + q.z, 0.f);
        float vw = __bfloat162float(h1.y) + __bfloat162float(l1.y) + fmaxf(p.w + q.w, 0.f);
        float hx = __bfloat162float(__float2bfloat16(vx));
        float hy = __bfloat162float(__float2bfloat16(vy));
        float hz = __bfloat162float(__float2bfloat16(vz));
        float hw = __bfloat162float(__float2bfloat16(vw));
        *(uint2*)(hB + off) = make_uint2(packbf(vx, vy), packbf(vz, vw));
        *(uint2*)(lB + off) = make_uint2(packbf(vx - hx, vy - hy),
                                         packbf(vz - hz, vw - hw));
        __syncwarp();
    }
}

__global__ void __launch_bounds__(256)
out_kernel(const float* __restrict__ H2, const float* __restrict__ Wc,
           const float* __restrict__ bc, float* __restrict__ out)
{
    int gw   = (blockIdx.x * blockDim.x + threadIdx.x) >> 5;
    int lane = threadIdx.x & 31;
    if (gw >= NODES) return;

    float4 hv  = ((const float4*)(H2 + (size_t)gw * HID))[lane];
    float4 w01 = ((const float4*)Wc)[lane * 2];
    float4 w23 = ((const float4*)Wc)[lane * 2 + 1];

    float a0 = hv.x * w01.x + hv.y * w01.z + hv.z * w23.x + hv.w * w23.z;
    float a1 = hv.x * w01.y + hv.y * w01.w + hv.z * w23.y + hv.w * w23.w;
#pragma unroll
    for (int off = 16; off > 0; off >>= 1) {
        a0 += __shfl_xor_sync(0xffffffffu, a0, off);
        a1 += __shfl_xor_sync(0xffffffffu, a1, off);
    }
    if (lane == 0) {
        out[(size_t)gw * 2]     = a0 + bc[0];
        out[(size_t)gw * 2 + 1] = a1 + bc[1];
    }
}

// ---------------------------------------------------------------------------
extern "C" void kernel_launch(void* const* d_in, const int* in_sizes, int n_in,
                              void* d_out, int out_size)
{
    const float* x    = (const float*)d_in[0];
    const int*   ei   = (const int*)d_in[1];
    const float* W_in = (const float*)d_in[2];
    const float* b_in = (const float*)d_in[3];
    const float* W1   = (const float*)d_in[4];
    const float* b1   = (const float*)d_in[5];
    const float* W2   = (const float*)d_in[6];
    const float* b2   = (const float*)d_in[7];
    const float* Wc   = (const float*)d_in[8];
    const float* bc   = (const float*)d_in[9];
    float*       out  = (float*)d_out;

    void *ph2, *pP, *pQ, *pcnt, *pWin, *pW1a, *pW1b, *pW2;
    void *phHi, *phLo, *psHi, *psLo;
    cudaGetSymbolAddress(&ph2,  g_h2);
    cudaGetSymbolAddress(&pP,   g_P);
    cudaGetSymbolAddress(&pQ,   g_Q);
    cudaGetSymbolAddress(&pcnt, g_cnt);
    cudaGetSymbolAddress(&pWin, g_iWin);
    cudaGetSymbolAddress(&pW1a, g_iW1a);
    cudaGetSymbolAddress(&pW1b, g_iW1b);
    cudaGetSymbolAddress(&pW2,  g_iW2);
    cudaGetSymbolAddress(&phHi, g_hHi);
    cudaGetSymbolAddress(&phLo, g_hLo);
    cudaGetSymbolAddress(&psHi, g_sHi);
    cudaGetSymbolAddress(&psLo, g_sLo);

    cudaFuncSetAttribute(gemm_a, cudaFuncAttributeMaxDynamicSharedMemorySize,
                         128 * 1024);
    cudaFuncSetAttribute(gemm_b, cudaFuncAttributeMaxDynamicSharedMemorySize,
                         192 * 1024);

    const int M = NODES;
    const int GRID = 148;

    prep_kernel<<<256, 256>>>(W_in, W1, W2);
    zero_kernel<<<256, 256>>>();
    bucket_kernel<<<(EDGES + 255) / 256, 256>>>(ei);

    // 1) h images = split(relu(x @ Win + b_in))
    gemm_a<<<GRID, 512, 128 * 1024>>>(x, (const uint4*)pWin, b_in,
                                      (uint4*)phHi, (uint4*)phLo, M, NTILES);
    // 2) P = h @ W1a + b1
    gemm_b<<<GRID, 512, 192 * 1024>>>((const uint4*)phHi, (const uint4*)phLo,
                                      (const uint4*)pW1a, b1, nullptr,
                                      (float*)pP, M, NTILES, 0);
    // 3) Q = h @ W1b
    gemm_b<<<GRID, 512, 192 * 1024>>>((const uint4*)phHi, (const uint4*)phLo,
                                      (const uint4*)pW1b, nullptr, nullptr,
                                      (float*)pQ, M, NTILES, 0);
    // 4) S images = split( sum_e relu(P[d]+Q[s]) )
    node_kernel<<<(NODES * 32 + 255) / 256, 256>>>();
    fixup_kernel<<<1, 32>>>();
    // 5) h2 = relu(S @ W2 + deg*b2)
    gemm_b<<<GRID, 512, 192 * 1024>>>((const uint4*)psHi, (const uint4*)psLo,
                                      (const uint4*)pW2, b2, (const int*)pcnt,
                                      (float*)ph2, M, NTILES, 1);
    // 6) out = h2 @ Wc + bc
    out_kernel<<<(NODES * 32 + 255) / 256, 256>>>((const float*)ph2, Wc, bc, out);
}